// round 14
// baseline (speedup 1.0000x reference)
#include <cuda_runtime.h>

#define RR 4
#define ND 81
#define HH 128
#define WW 256
#define CC 128
#define BB 8
#define HW (HH*WW)

#define HT 8                 // tile height
#define WT 16                // tile width
#define PW 4                 // pixels per thread (w)
#define CB 8                 // channels per stage
#define NCHUNK (CC/CB)       // 16
#define NSTG 3               // pipeline ring
#define WROWS (HT + 2*RR)    // 16
#define WROW 28              // warped row stride (floats); 24 used
#define XROW 20              // x row stride (floats); 19 used (16 + right halo @16 + left halo @18)
#define WCH (WROWS*WROW)     // 448
#define XCH (HT*XROW)        // 160
#define CHSZ (WCH + XCH)     // 608 floats / channel
#define STG (CB*CHSZ)        // 4864 floats / stage
#define MBAR_OFF (NSTG*STG*4)           // 58368
#define SMEM_BYTES (MBAR_OFF + 64)
#define NTHR 320             // 9 compute warps + 1 producer warp
#define NITEM 5              // staging items per producer lane (144 used of 160)

typedef unsigned long long u64t;

static __device__ __forceinline__ u64t pk2(float lo, float hi) {
    return __double_as_longlong(__hiloint2double(__float_as_int(hi), __float_as_int(lo)));
}
static __device__ __forceinline__ void fma2(u64t &acc, u64t a, u64t b) {
    asm("fma.rn.f32x2 %0, %1, %2, %0;" : "+l"(acc) : "l"(a), "l"(b));
}
static __device__ __forceinline__ float lo32(u64t v) {
    return __int_as_float(__double2loint(__longlong_as_double(v)));
}
static __device__ __forceinline__ float hi32(u64t v) {
    return __int_as_float(__double2hiint(__longlong_as_double(v)));
}
static __device__ __forceinline__ void cpa16(unsigned dst, const float* src) {
    asm volatile("cp.async.cg.shared.global [%0], [%1], 16;" :: "r"(dst), "l"(src));
}
static __device__ __forceinline__ void cpa4(unsigned dst, const float* src) {
    asm volatile("cp.async.ca.shared.global [%0], [%1], 4;" :: "r"(dst), "l"(src));
}
static __device__ __forceinline__ void mb_init(unsigned a, unsigned cnt) {
    asm volatile("mbarrier.init.shared.b64 [%0], %1;" :: "r"(a), "r"(cnt) : "memory");
}
static __device__ __forceinline__ void mb_arrive(unsigned a) {
    asm volatile("mbarrier.arrive.release.cta.shared::cta.b64 _, [%0];" :: "r"(a) : "memory");
}
static __device__ __forceinline__ void mb_wait(unsigned a, unsigned parity) {
    asm volatile(
        "{\n\t.reg .pred P1;\n\t"
        "WL_%=:\n\t"
        "mbarrier.try_wait.parity.acquire.cta.shared::cta.b64 P1, [%0], %1, 0x989680;\n\t"
        "@P1 bra.uni WD_%=;\n\t"
        "bra.uni WL_%=;\n\t"
        "WD_%=:\n\t}"
        :: "r"(a), "r"(parity) : "memory");
}

extern __shared__ __align__(16) float smf[];

__global__ void __launch_bounds__(NTHR, 3)
cost_volume_kernel(const float* __restrict__ gx, const float* __restrict__ gw,
                   float* __restrict__ gout)
{
    const int tid = threadIdx.x;
    const int w0  = blockIdx.x * WT;
    const int h0  = blockIdx.y * HT;
    const int b   = blockIdx.z;

    const float* xb = gx + (size_t)b * CC * HW;
    const float* wb = gw + (size_t)b * CC * HW;
    const unsigned smb = (unsigned)__cvta_generic_to_shared(smf);
    const unsigned mbF0 = smb + MBAR_OFF;   // full[s] at +s*16, empty[s] at +s*16+8

    if (tid == 0) {
        #pragma unroll
        for (int s = 0; s < NSTG; s++) {
            mb_init(mbF0 + s * 16, 32);      // full: 32 producer lanes
            mb_init(mbF0 + s * 16 + 8, 9);   // empty: 9 consumer warp-elects
        }
    }
    // OOB slots are channel-independent: zero once in every ring stage
    if (tid < 96) {                          // warped halo 16 rows x 6 quads
        const int row = tid / 6, q = tid % 6;
        const int gh   = h0 - RR + row;
        const int gcol = w0 - RR + q * 4;
        if (!(((unsigned)gh < HH) && (gcol >= 0) && (gcol + 4 <= WW))) {
            const int so = row * WROW + q * 4;
            for (int s = 0; s < NSTG; s++)
                for (int cc2 = 0; cc2 < CB; cc2++)
                    *(float4*)(smf + s * STG + cc2 * CHSZ + so) =
                        make_float4(0.f, 0.f, 0.f, 0.f);
        }
    } else if (tid < 104) {                  // x left halo col (offset 18), row = tid-96
        if (w0 == 0) {
            const int so = WCH + (tid - 96) * XROW + 18;
            for (int s = 0; s < NSTG; s++)
                for (int cc2 = 0; cc2 < CB; cc2++)
                    smf[s * STG + cc2 * CHSZ + so] = 0.0f;
        }
    } else if (tid < 112) {                  // x right halo col (offset 16), row = tid-104
        if (w0 + WT >= WW) {
            const int so = WCH + (tid - 104) * XROW + 16;
            for (int s = 0; s < NSTG; s++)
                for (int cc2 = 0; cc2 < CB; cc2++)
                    smf[s * STG + cc2 * CHSZ + so] = 0.0f;
        }
    }
    __syncthreads();

    if (tid >= 288) {
        // ================= producer warp =================
        const int lane = tid - 288;
        const float* src[NITEM]; unsigned doff[NITEM]; bool val[NITEM]; bool big[NITEM];
        #pragma unroll
        for (int k = 0; k < NITEM; k++) {
            const int it = lane + 32 * k;
            val[k] = false; big[k] = true; src[k] = wb; doff[k] = 0;
            if (it < 96) {                       // warped halo quads
                const int row = it / 6, q = it % 6;
                const int gh   = h0 - RR + row;
                const int gcol = w0 - RR + q * 4;
                doff[k] = (unsigned)((row * WROW + q * 4) * 4);
                val[k]  = ((unsigned)gh < HH) && (gcol >= 0) && (gcol + 4 <= WW);
                if (val[k]) src[k] = wb + (size_t)gh * WW + gcol;
            } else if (it < 128) {               // x quads 8 rows x 4
                const int i = it - 96;
                const int row = i / 4, q = i % 4;
                doff[k] = (unsigned)((WCH + row * XROW + q * 4) * 4);
                src[k]  = xb + (size_t)(h0 + row) * WW + w0 + q * 4;
                val[k]  = true;
            } else if (it < 136) {               // x left halo (w0-1) -> offset 18
                const int row = it - 128;
                doff[k] = (unsigned)((WCH + row * XROW + 18) * 4);
                big[k]  = false;
                val[k]  = (w0 > 0);
                if (val[k]) src[k] = xb + (size_t)(h0 + row) * WW + w0 - 1;
            } else if (it < 144) {               // x right halo (w0+16) -> offset 16
                const int row = it - 136;
                doff[k] = (unsigned)((WCH + row * XROW + 16) * 4);
                big[k]  = false;
                val[k]  = (w0 + WT < WW);
                if (val[k]) src[k] = xb + (size_t)(h0 + row) * WW + w0 + WT;
            }
        }

        int es = 0, eph = 0;
        int ps = 0, prev = 0;
        #pragma unroll 1
        for (int chunk = 0; chunk < NCHUNK; chunk++) {
            if (chunk >= NSTG) {
                mb_wait(mbF0 + es * 16 + 8, (unsigned)eph);
                if (++es == NSTG) { es = 0; eph ^= 1; }
            }
            const unsigned sb = smb + (unsigned)(ps * STG * 4);
            #pragma unroll
            for (int cc = 0; cc < CB; cc++) {
                #pragma unroll
                for (int k = 0; k < NITEM; k++)
                    if (val[k]) {
                        if (big[k]) cpa16(sb + doff[k] + (unsigned)(cc * CHSZ * 4), src[k] + cc * HW);
                        else        cpa4 (sb + doff[k] + (unsigned)(cc * CHSZ * 4), src[k] + cc * HW);
                    }
            }
            #pragma unroll
            for (int k = 0; k < NITEM; k++) src[k] += CB * HW;
            asm volatile("cp.async.commit_group;" ::: "memory");
            if (chunk >= 1) {
                asm volatile("cp.async.wait_group 1;" ::: "memory");
                mb_arrive(mbF0 + prev * 16);
            }
            prev = ps;
            if (++ps == NSTG) ps = 0;
        }
        asm volatile("cp.async.wait_group 0;" ::: "memory");
        mb_arrive(mbF0 + prev * 16);
    } else {
        // ================= consumer warps =================
        const int dig = tid % 9;        // di + 4
        const int hwg = tid / 9;        // 0..31
        const int h_i = hwg & 7;
        const int wg  = hwg >> 3;       // 0..3

        const int woff  = (h_i + dig) * WROW + wg * PW;    // warped window base (16B aligned)
        const int xoff  = WCH + h_i * XROW + wg * PW;      // x quad (16B aligned)
        const int xm1o  = (wg == 0) ? (WCH + h_i * XROW + 18) : (xoff - 1);  // x[base-1]
        const int x4o   = xoff + 4;                        // x[base+4] (offset 16 for wg==3)

        // accumulators: evens djg=2k (k 0..4) x 2 pairs; up djg=2k+1; down djg=2k+5
        u64t accE[10], accU[4], accD[4];
        #pragma unroll
        for (int i = 0; i < 10; i++) accE[i] = 0ULL;
        #pragma unroll
        for (int i = 0; i < 4; i++) { accU[i] = 0ULL; accD[i] = 0ULL; }

        int st = 0, ph = 0;
        #pragma unroll 1
        for (int chunk = 0; chunk < NCHUNK; chunk++) {
            mb_wait(mbF0 + st * 16, (unsigned)ph);

            const float* sb = smf + st * STG;
            #pragma unroll
            for (int cc2 = 0; cc2 < CB; cc2++) {
                const float* base = sb + cc2 * CHSZ;
                const float4* wv4 = (const float4*)(base + woff);

                float4 q0 = wv4[0], q1 = wv4[1], q2 = wv4[2];
                float4 xq = *(const float4*)(base + xoff);
                float xm1 = base[xm1o];
                float x4  = base[x4o];

                // 6 aligned warped pairs (free register pairs)
                u64t P[6];
                P[0] = pk2(q0.x, q0.y); P[1] = pk2(q0.z, q0.w);
                P[2] = pk2(q1.x, q1.y); P[3] = pk2(q1.z, q1.w);
                P[4] = pk2(q2.x, q2.y); P[5] = pk2(q2.z, q2.w);

                // x pairs: even free; odd built once each
                u64t xe0 = pk2(xq.x, xq.y), xe1 = pk2(xq.z, xq.w);
                u64t B1 = pk2(xm1, xq.x);     // (x[-1], x[0])
                u64t B2 = pk2(xq.y, xq.z);    // (x[1], x[2])
                u64t B3 = pk2(xq.w, x4);      // (x[3], x[4])

                #pragma unroll
                for (int k = 0; k < 5; k++) {          // djg = 2k
                    fma2(accE[k * 2 + 0], xe0, P[k]);
                    fma2(accE[k * 2 + 1], xe1, P[k + 1]);
                }
                #pragma unroll
                for (int k = 0; k < 2; k++) {          // djg = 2k+1 (up pairing)
                    fma2(accU[k * 2 + 0], B2, P[k + 1]);
                    fma2(accU[k * 2 + 1], B3, P[k + 2]);
                }
                #pragma unroll
                for (int k = 0; k < 2; k++) {          // djg = 2k+5 (down pairing)
                    fma2(accD[k * 2 + 0], B1, P[k + 2]);
                    fma2(accD[k * 2 + 1], B2, P[k + 3]);
                }
            }

            if ((tid & 31) == 0) mb_arrive(mbF0 + st * 16 + 8);
            if (++st == NSTG) { st = 0; ph ^= 1; }
        }

        // ---------------- epilogue ----------------
        const float sc = 1.0f / (float)(CC * ND);
        const int basew = w0 + wg * PW;
        float* rowp = gout + (((size_t)b * ND + dig * 9) * HH + (h0 + h_i)) * WW;

        #pragma unroll
        for (int k = 0; k < 5; k++) {                  // djg = 2k, aligned float2 stores
            float* od = rowp + (size_t)(2 * k) * HW + basew;
            float2 r0, r1;
            r0.x = lo32(accE[k*2+0]) * sc;  r0.y = hi32(accE[k*2+0]) * sc;
            r1.x = lo32(accE[k*2+1]) * sc;  r1.y = hi32(accE[k*2+1]) * sc;
            *(float2*)(od)     = r0;
            *(float2*)(od + 2) = r1;
        }
        #pragma unroll
        for (int k = 0; k < 2; k++) {                  // djg = 2k+1, pixels basew+1..+4
            float* od = rowp + (size_t)(2 * k + 1) * HW;
            #pragma unroll
            for (int j = 0; j < 2; j++) {
                const int g0 = basew + 1 + 2 * j;
                od[g0] = lo32(accU[k*2+j]) * sc;
                if (g0 + 1 < WW) od[g0 + 1] = hi32(accU[k*2+j]) * sc;
            }
        }
        #pragma unroll
        for (int k = 0; k < 2; k++) {                  // djg = 2k+5, pixels basew-1..+2
            float* od = rowp + (size_t)(2 * k + 5) * HW;
            #pragma unroll
            for (int j = 0; j < 2; j++) {
                const int g0 = basew - 1 + 2 * j;
                if (g0 >= 0) od[g0] = lo32(accD[k*2+j]) * sc;
                od[g0 + 1] = hi32(accD[k*2+j]) * sc;
            }
        }
        // edge zeros (reference zero-padding makes these exactly 0)
        if (w0 == 0 && wg == 0) {
            rowp[(size_t)1 * HW] = 0.0f;
            rowp[(size_t)3 * HW] = 0.0f;
        }
        if (w0 + WT == WW && wg == 3) {
            rowp[(size_t)5 * HW + (WW - 1)] = 0.0f;
            rowp[(size_t)7 * HW + (WW - 1)] = 0.0f;
        }
    }
}

extern "C" void kernel_launch(void* const* d_in, const int* in_sizes, int n_in,
                              void* d_out, int out_size) {
    const float* x = (const float*)d_in[0];
    const float* w = (const float*)d_in[1];
    float* out = (float*)d_out;
    cudaFuncSetAttribute(cost_volume_kernel,
                         cudaFuncAttributeMaxDynamicSharedMemorySize, SMEM_BYTES);
    dim3 grid(WW / WT, HH / HT, BB);   // (16, 16, 8) = 2048 blocks
    cost_volume_kernel<<<grid, NTHR, SMEM_BYTES>>>(x, w, out);
}